// round 2
// baseline (speedup 1.0000x reference)
#include <cuda_runtime.h>
#include <cuda_bf16.h>
#include <stdint.h>

#define B 128
#define C 1024
#define MARGIN 1.0f
#define THREADS 256
#define MAX_POS 256

// Per-row partials (deterministic, no float atomics across blocks)
__device__ float g_loss[B];
__device__ float g_npos[B];

// Mask dtype detection flags. Zero-initialized at module load; only ever
// atomicOr'd with the same input-dependent bits -> idempotent across graph
// replays, so kernel_launch stays deterministic.
//   bit 0: saw word == 0x3f800000 (float32 1.0)  -> mask is float32
//   bit 1: saw word with nonzero byte above byte0 -> mask is packed uint8 bools
//   neither: words are 0/1 -> mask is int32
__device__ unsigned int g_maskinfo;

__global__ void detect_mask_dtype(const uint32_t* __restrict__ mw) {
    // Scan 32768 words = min buffer size across dtype hypotheses (uint8 case).
    unsigned int local = 0;
    for (int i = blockIdx.x * blockDim.x + threadIdx.x; i < 32768;
         i += gridDim.x * blockDim.x) {
        uint32_t w = mw[i];
        if (w == 0x3f800000u)            local |= 1u;
        else if (w & 0xFFFFFF00u)        local |= 2u;
    }
    // warp-reduce then one atomic per warp
    for (int off = 16; off > 0; off >>= 1)
        local |= __shfl_down_sync(0xFFFFFFFFu, local, off);
    if ((threadIdx.x & 31) == 0 && local) atomicOr(&g_maskinfo, local);
}

__global__ void __launch_bounds__(THREADS)
row_kernel(const float* __restrict__ scores, const void* __restrict__ pos_mask) {
    const int row = blockIdx.x;
    const int tid = threadIdx.x;

    const unsigned int info = g_maskinfo;
    const bool isF32 = (info & 1u) != 0u;
    const bool isU8  = !isF32 && ((info & 2u) != 0u);

    __shared__ float s_pos[MAX_POS];
    __shared__ int   s_npos;
    __shared__ float s_red[THREADS / 32];

    if (tid == 0) s_npos = 0;
    __syncthreads();

    const float* srow = scores + row * C;

    float my_scores[C / THREADS];
    unsigned char my_mask[C / THREADS];

#pragma unroll
    for (int k = 0; k < C / THREADS; k++) {
        int j = tid + k * THREADS;
        my_scores[k] = srow[j];
        int idx = row * C + j;
        unsigned char pm;
        if (isF32) {
            pm = (((const float*)pos_mask)[idx] != 0.0f) ? 1 : 0;
        } else if (isU8) {
            pm = (((const unsigned char*)pos_mask)[idx] != 0) ? 1 : 0;
        } else {
            pm = (((const int*)pos_mask)[idx] != 0) ? 1 : 0;
        }
        my_mask[k] = pm;
        if (pm) {
            int slot = atomicAdd(&s_npos, 1);
            if (slot < MAX_POS) s_pos[slot] = my_scores[k];
        }
    }
    __syncthreads();

    const int npos = min(s_npos, MAX_POS);

    float acc = 0.0f;
#pragma unroll
    for (int k = 0; k < C / THREADS; k++) {
        if (!my_mask[k]) {
            const float sn = my_scores[k] + MARGIN;
            for (int p = 0; p < npos; p++) {
                acc += fmaxf(sn - s_pos[p], 0.0f);
            }
        }
    }

#pragma unroll
    for (int off = 16; off > 0; off >>= 1)
        acc += __shfl_down_sync(0xFFFFFFFFu, acc, off);
    if ((tid & 31) == 0) s_red[tid >> 5] = acc;
    __syncthreads();
    if (tid == 0) {
        float total = 0.0f;
#pragma unroll
        for (int w = 0; w < THREADS / 32; w++) total += s_red[w];
        g_loss[row] = total;
        g_npos[row] = (float)npos;
    }
}

__global__ void __launch_bounds__(128)
final_kernel(float* __restrict__ out) {
    const int tid = threadIdx.x;  // 128 threads, one per row
    float l = g_loss[tid];
    float np = g_npos[tid];
    float d = np * (float)(C - (int)np);

    __shared__ float s_l[4], s_d[4];
#pragma unroll
    for (int off = 16; off > 0; off >>= 1) {
        l += __shfl_down_sync(0xFFFFFFFFu, l, off);
        d += __shfl_down_sync(0xFFFFFFFFu, d, off);
    }
    if ((tid & 31) == 0) { s_l[tid >> 5] = l; s_d[tid >> 5] = d; }
    __syncthreads();
    if (tid == 0) {
        float L = s_l[0] + s_l[1] + s_l[2] + s_l[3];
        float D = s_d[0] + s_d[1] + s_d[2] + s_d[3];
        out[0] = (D == 0.0f) ? 0.0f : L / D;
    }
}

extern "C" void kernel_launch(void* const* d_in, const int* in_sizes, int n_in,
                              void* d_out, int out_size) {
    const float* scores = (const float*)d_in[0];
    const void* pos_mask = d_in[1];
    float* out = (float*)d_out;

    detect_mask_dtype<<<32, 256>>>((const uint32_t*)pos_mask);
    row_kernel<<<B, THREADS>>>(scores, pos_mask);
    final_kernel<<<1, 128>>>(out);
}

// round 3
// speedup vs baseline: 1.2647x; 1.2647x over previous
#include <cuda_runtime.h>
#include <cuda_bf16.h>
#include <stdint.h>

#define B 128
#define C 1024
#define MARGIN 1.0f
#define THREADS 256
#define MAX_POS 256
#define DETECT_WORDS 2048   // 8 KB scanned per block (broadcast from L2)

// Per-row partials (deterministic, no float atomics across blocks)
__device__ float g_loss[B];
__device__ float g_npos[B];
// Last-block-done ticket; reset to 0 by the finishing block -> replay-safe.
__device__ unsigned int g_ticket;

__global__ void __launch_bounds__(THREADS)
fused_kernel(const float* __restrict__ scores, const void* __restrict__ pos_mask,
             float* __restrict__ out) {
    const int row = blockIdx.x;
    const int tid = threadIdx.x;

    __shared__ unsigned int s_info;
    __shared__ float s_pos[MAX_POS];
    __shared__ int   s_npos;
    __shared__ float s_red[THREADS / 32];
    __shared__ int   s_last;

    if (tid == 0) { s_info = 0; s_npos = 0; }
    __syncthreads();

    // ---- Per-block mask dtype detection (same logic that gave rel_err=0) ----
    //   bit 0: word == 0x3f800000 (float 1.0)      -> float32 mask
    //   bit 1: word has nonzero bytes above byte0  -> packed uint8 bools
    //   neither: words are 0/1                     -> int32 mask
    {
        const uint32_t* mw = (const uint32_t*)pos_mask;
        unsigned int local = 0;
#pragma unroll
        for (int k = 0; k < DETECT_WORDS / THREADS; k++) {
            uint32_t w = mw[tid + k * THREADS];
            if (w == 0x3f800000u)     local |= 1u;
            else if (w & 0xFFFFFF00u) local |= 2u;
        }
#pragma unroll
        for (int off = 16; off > 0; off >>= 1)
            local |= __shfl_down_sync(0xFFFFFFFFu, local, off);
        if ((tid & 31) == 0 && local) atomicOr(&s_info, local);
    }
    __syncthreads();

    const unsigned int info = s_info;
    const bool isF32 = (info & 1u) != 0u;
    const bool isU8  = !isF32 && ((info & 2u) != 0u);

    // ---- Load row, gather positives into SMEM ----
    const float* srow = scores + row * C;

    float my_scores[C / THREADS];
    unsigned char my_mask[C / THREADS];

#pragma unroll
    for (int k = 0; k < C / THREADS; k++) {
        int j = tid + k * THREADS;
        my_scores[k] = srow[j];
        int idx = row * C + j;
        unsigned char pm;
        if (isF32)     pm = (((const float*)pos_mask)[idx] != 0.0f) ? 1 : 0;
        else if (isU8) pm = (((const unsigned char*)pos_mask)[idx] != 0) ? 1 : 0;
        else           pm = (((const int*)pos_mask)[idx] != 0) ? 1 : 0;
        my_mask[k] = pm;
        if (pm) {
            int slot = atomicAdd(&s_npos, 1);
            if (slot < MAX_POS) s_pos[slot] = my_scores[k];
        }
    }
    __syncthreads();

    const int npos = min(s_npos, MAX_POS);

    // ---- Pairwise hinge: each thread's negatives vs all positives ----
    float acc = 0.0f;
#pragma unroll
    for (int k = 0; k < C / THREADS; k++) {
        if (!my_mask[k]) {
            const float sn = my_scores[k] + MARGIN;
            for (int p = 0; p < npos; p++)
                acc += fmaxf(sn - s_pos[p], 0.0f);
        }
    }

    // ---- Deterministic block reduction ----
#pragma unroll
    for (int off = 16; off > 0; off >>= 1)
        acc += __shfl_down_sync(0xFFFFFFFFu, acc, off);
    if ((tid & 31) == 0) s_red[tid >> 5] = acc;
    __syncthreads();

    if (tid == 0) {
        float total = 0.0f;
#pragma unroll
        for (int w = 0; w < THREADS / 32; w++) total += s_red[w];
        g_loss[row] = total;
        g_npos[row] = (float)npos;
        __threadfence();
        unsigned int ticket = atomicAdd(&g_ticket, 1u);
        s_last = (ticket == B - 1) ? 1 : 0;
    }
    __syncthreads();

    // ---- Last block finalizes (fixed-order, bitwise deterministic) ----
    if (s_last) {
        __threadfence();  // acquire: partials from all blocks visible
        if (tid < B) {
            float l  = g_loss[tid];
            float np = g_npos[tid];
            float d  = np * (float)(C - (int)np);
#pragma unroll
            for (int off = 16; off > 0; off >>= 1) {
                l += __shfl_down_sync(0xFFFFFFFFu, l, off);
                d += __shfl_down_sync(0xFFFFFFFFu, d, off);
            }
            if ((tid & 31) == 0) {
                s_red[tid >> 5] = l;
                s_pos[tid >> 5] = d;   // reuse smem
            }
        }
        __syncthreads();
        if (tid == 0) {
            float L = s_red[0] + s_red[1] + s_red[2] + s_red[3];
            float D = s_pos[0] + s_pos[1] + s_pos[2] + s_pos[3];
            out[0] = (D == 0.0f) ? 0.0f : L / D;
            g_ticket = 0;  // reset for next graph replay
        }
    }
}

extern "C" void kernel_launch(void* const* d_in, const int* in_sizes, int n_in,
                              void* d_out, int out_size) {
    const float* scores = (const float*)d_in[0];
    const void* pos_mask = d_in[1];
    float* out = (float*)d_out;

    fused_kernel<<<B, THREADS>>>(scores, pos_mask, out);
}

// round 4
// speedup vs baseline: 1.2694x; 1.0037x over previous
#include <cuda_runtime.h>
#include <cuda_bf16.h>
#include <stdint.h>

#define B 128
#define C 1024
#define MARGIN 1.0f
#define THREADS 256
#define MAX_POS 256
#define VEC 4                 // elements per thread (C / THREADS)

// Per-row partials (deterministic, no float atomics across blocks)
__device__ float g_loss[B];
__device__ float g_npos[B];
// Last-block-done ticket; reset to 0 by the finishing block -> replay-safe.
__device__ unsigned int g_ticket;

__global__ void __launch_bounds__(THREADS, 1)
fused_kernel(const float* __restrict__ scores, const void* __restrict__ pos_mask,
             float* __restrict__ out) {
    const int row = blockIdx.x;
    const int tid = threadIdx.x;

    __shared__ unsigned int s_info;
    __shared__ float s_pos[MAX_POS];
    __shared__ int   s_npos;
    __shared__ float s_red[THREADS / 32];
    __shared__ int   s_last;

    if (tid == 0) { s_info = 0; s_npos = 0; }

    // ---- Issue score load FIRST (independent of dtype detection) ----
    const float4 sc4 = ((const float4*)(scores + row * C))[tid];
    float sc[VEC] = {sc4.x, sc4.y, sc4.z, sc4.w};

    // ---- Mask dtype detection: scan first 2048 words (8KB), vectorized ----
    //   bit 0: word == 0x3f800000 (float 1.0)      -> float32 mask
    //   bit 1: word has nonzero bytes above byte0  -> packed uint8 bools
    //   neither: words are 0/1                     -> int32 mask
    {
        const uint4* dw = (const uint4*)pos_mask;
        uint4 a = dw[tid * 2];
        uint4 b = dw[tid * 2 + 1];
        unsigned int local = 0;
        uint32_t w[8] = {a.x, a.y, a.z, a.w, b.x, b.y, b.z, b.w};
#pragma unroll
        for (int i = 0; i < 8; i++) {
            if (w[i] == 0x3f800000u)     local |= 1u;
            else if (w[i] & 0xFFFFFF00u) local |= 2u;
        }
        local = __reduce_or_sync(0xFFFFFFFFu, local);
        if ((tid & 31) == 0 && local) atomicOr(&s_info, local);
    }
    __syncthreads();

    const unsigned int info = s_info;

    // ---- Load this thread's 4 mask elements under the detected dtype ----
    unsigned char m[VEC];
    if (info & 1u) {                    // float32 mask
        float4 mv = ((const float4*)pos_mask)[row * (C / VEC) + tid];
        m[0] = mv.x != 0.0f; m[1] = mv.y != 0.0f;
        m[2] = mv.z != 0.0f; m[3] = mv.w != 0.0f;
    } else if (info & 2u) {             // packed uint8 bools
        uint32_t mv = ((const uint32_t*)pos_mask)[row * (C / VEC) + tid];
        m[0] = (mv & 0x000000FFu) != 0; m[1] = (mv & 0x0000FF00u) != 0;
        m[2] = (mv & 0x00FF0000u) != 0; m[3] = (mv & 0xFF000000u) != 0;
    } else {                            // int32 mask
        uint4 mv = ((const uint4*)pos_mask)[row * (C / VEC) + tid];
        m[0] = mv.x != 0; m[1] = mv.y != 0; m[2] = mv.z != 0; m[3] = mv.w != 0;
    }

    // ---- Gather positive scores into SMEM ----
#pragma unroll
    for (int k = 0; k < VEC; k++) {
        if (m[k]) {
            int slot = atomicAdd(&s_npos, 1);
            if (slot < MAX_POS) s_pos[slot] = sc[k];
        }
    }
    __syncthreads();

    const int npos = min(s_npos, MAX_POS);

    // ---- Pairwise hinge: this thread's negatives vs all positives ----
    float acc = 0.0f;
#pragma unroll
    for (int k = 0; k < VEC; k++) {
        if (!m[k]) {
            const float sn = sc[k] + MARGIN;
            for (int p = 0; p < npos; p++)
                acc += fmaxf(sn - s_pos[p], 0.0f);
        }
    }

    // ---- Deterministic block reduction ----
#pragma unroll
    for (int off = 16; off > 0; off >>= 1)
        acc += __shfl_down_sync(0xFFFFFFFFu, acc, off);
    if ((tid & 31) == 0) s_red[tid >> 5] = acc;
    __syncthreads();

    if (tid == 0) {
        float total = 0.0f;
#pragma unroll
        for (int w = 0; w < THREADS / 32; w++) total += s_red[w];
        g_loss[row] = total;
        g_npos[row] = (float)npos;
        __threadfence();
        unsigned int ticket = atomicAdd(&g_ticket, 1u);
        s_last = (ticket == B - 1) ? 1 : 0;
    }
    __syncthreads();

    // ---- Last block finalizes (fixed-order, bitwise deterministic) ----
    if (s_last) {
        __threadfence();  // acquire: all blocks' partials visible
        if (tid < B) {
            float l  = g_loss[tid];
            float np = g_npos[tid];
            float d  = np * (float)(C - (int)np);
#pragma unroll
            for (int off = 16; off > 0; off >>= 1) {
                l += __shfl_down_sync(0xFFFFFFFFu, l, off);
                d += __shfl_down_sync(0xFFFFFFFFu, d, off);
            }
            if ((tid & 31) == 0) {
                s_red[tid >> 5] = l;
                s_pos[tid >> 5] = d;   // reuse smem
            }
        }
        __syncthreads();
        if (tid == 0) {
            float L = s_red[0] + s_red[1] + s_red[2] + s_red[3];
            float D = s_pos[0] + s_pos[1] + s_pos[2] + s_pos[3];
            out[0] = (D == 0.0f) ? 0.0f : L / D;
            g_ticket = 0;  // reset for next graph replay
        }
    }
}

extern "C" void kernel_launch(void* const* d_in, const int* in_sizes, int n_in,
                              void* d_out, int out_size) {
    const float* scores = (const float*)d_in[0];
    const void* pos_mask = d_in[1];
    float* out = (float*)d_out;

    fused_kernel<<<B, THREADS>>>(scores, pos_mask, out);
}